// round 8
// baseline (speedup 1.0000x reference)
#include <cuda_runtime.h>

// ---------------------------------------------------------------------------
// Fused MoE via grouped fp16 mma.sync (m16n8k16) GEMMs, fp32 accumulate.
//   T=1024, H=2048, F=1408, E=32, K=6.
// zero_out -> prep(one CTA: detect/hist/scan/fill) ->
// GEMM1 (gate+up in one CTA, fused SwiGLU epilogue -> d_Hb) ->
// GEMM2 (fused weighted atomic scatter -> out)
// M-stripes interleaved across SMSPs at 16-row grain so expert-count padding
// idles no sub-partition.
// ---------------------------------------------------------------------------

#define T_TOK 1024
#define HID   2048
#define FF    1408
#define NEXP  32
#define TOPK  6
#define NA    (T_TOK * TOPK)    // 6144
#define GUN   (2 * FF)          // 2816

typedef unsigned int u32;

// smem: A 3 stages x 256 rows x 40 floats; B 3 stages x 128 rows x 40 floats
#define AST   40960u
#define BBASE 122880u
#define BST   20480u
#define SMB   184320
#define XSTR  68                // exchange stride (floats)

// ---------------- device scratch -------------------------------------------
__device__ int   d_count[NEXP];
__device__ int   d_off[NEXP];
__device__ int   d_tok[NA];
__device__ float d_wts[NA];
__device__ float d_Hb[(size_t)NA * FF];

// ---------------- PTX helpers ----------------------------------------------
__device__ __forceinline__ u32 smem_u32(const void* p) {
    u32 a;
    asm("{ .reg .u64 t; cvta.to.shared.u64 t, %1; cvt.u32.u64 %0, t; }"
        : "=r"(a) : "l"(p));
    return a;
}
__device__ __forceinline__ u32 pack2h(float2 v) {   // {lo=v.x, hi=v.y} fp16x2
    u32 r;
    asm("cvt.rn.f16x2.f32 %0, %1, %2;" : "=r"(r) : "f"(v.y), "f"(v.x));
    return r;
}
#define CP16(dst, src, sz) \
    asm volatile("cp.async.cg.shared.global [%0], [%1], 16, %2;" \
                 :: "r"(dst), "l"(src), "r"(sz))
#define CP_COMMIT() asm volatile("cp.async.commit_group;" ::: "memory")
#define CP_WAIT(n)  asm volatile("cp.async.wait_group %0;" :: "n"(n) : "memory")

__device__ __forceinline__ void mma16(float* d, u32 a0, u32 a1, u32 a2, u32 a3,
                                      u32 b0, u32 b1) {
    asm volatile(
        "mma.sync.aligned.m16n8k16.row.col.f32.f16.f16.f32 "
        "{%0,%1,%2,%3}, {%4,%5,%6,%7}, {%8,%9}, {%0,%1,%2,%3};"
        : "+f"(d[0]), "+f"(d[1]), "+f"(d[2]), "+f"(d[3])
        : "r"(a0), "r"(a1), "r"(a2), "r"(a3), "r"(b0), "r"(b1));
}

// ---------------- prep: detect + hist + scan + fill, one CTA ----------------
__global__ void k_zero_out(float4* out) {
    out[blockIdx.x * blockDim.x + threadIdx.x] = make_float4(0.f, 0.f, 0.f, 0.f);
}
__global__ __launch_bounds__(256) void k_prep(const int* __restrict__ ids32,
                                              const float* __restrict__ tw) {
    __shared__ int f;
    __shared__ int scnt[NEXP];
    __shared__ int sfill[NEXP];
    const int tid = threadIdx.x;
    if (tid < NEXP) scnt[tid] = 0;
    if (tid == 0) f = 0;
    __syncthreads();
    int local = 0;
    for (int i = tid; i < NA / 2; i += 256)
        if (ids32[2 * i + 1] != 0) local = 1;
    if (local) f = 1;
    __syncthreads();
    const int flag = f;   // 1 => int32 ids
    for (int i = tid; i < NA; i += 256) {
        int e = flag ? ids32[i] : ids32[2 * i];
        atomicAdd(&scnt[e], 1);
    }
    __syncthreads();
    if (tid == 0) {
        int off = 0;
        for (int e = 0; e < NEXP; e++) {
            d_off[e] = off; sfill[e] = off;
            d_count[e] = scnt[e];
            off += scnt[e];
        }
    }
    __syncthreads();
    for (int i = tid; i < NA; i += 256) {
        int e = flag ? ids32[i] : ids32[2 * i];
        int pos = atomicAdd(&sfill[e], 1);
        d_tok[pos] = i / TOPK;
        d_wts[pos] = tw[i];
    }
}

// ---------------- grouped fp16 GEMM ----------------------------------------
// BM=256, BK=32, 256 threads (8 warps).  Warp covers four 16-row stripes at
// rows (wid&3)*16 + mt*64 x 64 cols.
// MODE 0 (GEMM1): B tile = 64 gate rows + 64 up rows of the same h-columns
//   (n0=blockIdx.x*64). Warp group 0 computes gate, group 1 up; epilogue
//   exchanges up accs through smem, applies silu(g)*u, writes d_Hb.
// MODE 1 (GEMM2): BN=128 (n0=blockIdx.x*128), weighted atomic scatter to Out.
template<int KDIM, int MODE>
__global__ __launch_bounds__(256, 1) void k_gemm(const float* __restrict__ Ain,
                                                 const float* __restrict__ Bw,
                                                 float* __restrict__ Out) {
    constexpr int NIT = KDIM / 32;
    extern __shared__ char smem[];
    const int e = blockIdx.y;
    const int cnt = d_count[e];
    if (cnt == 0) return;
    const int row0e = d_off[e];
    const int n0 = blockIdx.x * (MODE == 0 ? 64 : 128);
    const long long bStride = (MODE == 0) ? (long long)GUN * HID
                                          : (long long)HID * FF;
    const float* A = (MODE == 0) ? Ain : d_Hb;

    const int tid = threadIdx.x;
    const int wid = tid >> 5, lane = tid & 31;
    const int r4 = lane >> 2, c4 = lane & 3;
    const int s16   = (wid & 3) * 16;       // SMSP-interleaved M base
    const int group = wid >> 2;             // MODE0: 0=gate 1=up
    const int warpN = group * 64;           // MODE1 column half
    const u32 sb = smem_u32(smem);

    const int chunk = tid & 7, rb = tid >> 3;
    const float* bS[4];
    u32 bD[4];
#pragma unroll
    for (int p = 0; p < 4; p++) {
        int row = rb + 32 * p;
        long long gr = (MODE == 0)
            ? ((row < 64) ? (long long)(n0 + row) : (long long)(FF + n0 + row - 64))
            : (long long)(n0 + row);
        bS[p] = Bw + (long long)e * bStride + gr * KDIM + chunk * 4;
        bD[p] = sb + BBASE + (u32)row * 160u + (u32)chunk * 16u;
    }

    for (int m0 = 0; m0 < cnt; m0 += 256) {
        const float* aS[8];
        u32 aV[8], aD[8];
#pragma unroll
        for (int j = 0; j < 8; j++) {
            int r = rb + 32 * j;
            int valid = (m0 + r) < cnt;
            long long src = 0;
            if (valid)
                src = (MODE == 0) ? (long long)d_tok[row0e + m0 + r]
                                  : (long long)(row0e + m0 + r);
            aS[j] = A + src * KDIM + chunk * 4;
            aV[j] = valid ? 16u : 0u;
            aD[j] = sb + (u32)r * 160u + (u32)chunk * 16u;
        }
        const int rem = cnt - m0;
        const int tv = rem - s16;
        const int mtMax = (tv <= 0) ? 0 : ((tv + 63) >> 6 > 4 ? 4 : (tv + 63) >> 6);

        float acc[4][8][4];
#pragma unroll
        for (int mt = 0; mt < 4; mt++)
#pragma unroll
            for (int nt = 0; nt < 8; nt++)
#pragma unroll
                for (int q = 0; q < 4; q++) acc[mt][nt][q] = 0.f;

#define ISSUE(s, k0) do {                                                  \
        u32 _ao = (u32)(s) * AST;                                          \
        u32 _bo = (u32)(s) * BST;                                          \
        _Pragma("unroll")                                                  \
        for (int _j = 0; _j < 8; _j++)                                     \
            CP16(aD[_j] + _ao, aS[_j] + (k0), aV[_j]);                     \
        _Pragma("unroll")                                                  \
        for (int _p = 0; _p < 4; _p++)                                     \
            CP16(bD[_p] + _bo, bS[_p] + (k0), 16u);                        \
    } while (0)

        ISSUE(0, 0);  CP_COMMIT();
        ISSUE(1, 32); CP_COMMIT();

        for (int it = 0; it < NIT; it++) {
            const int buf = it % 3;
            CP_WAIT(1);
            __syncthreads();
            const int ns = it + 2;
            if (ns < NIT) ISSUE(ns % 3, ns * 32);
            CP_COMMIT();

            const float* Af = (const float*)(smem + buf * AST);
            const float* Bf = (const float*)(smem + BBASE + buf * BST);
#pragma unroll
            for (int ks = 0; ks < 2; ks++) {
                u32 b[8][2];
#pragma unroll
                for (int nt = 0; nt < 8; nt++) {
                    int cb = (warpN + nt * 8 + r4) * 40 + ks * 16 + 2 * c4;
                    b[nt][0] = pack2h(*(const float2*)&Bf[cb]);
                    b[nt][1] = pack2h(*(const float2*)&Bf[cb + 8]);
                }
#pragma unroll
                for (int mt = 0; mt < 4; mt++) {
                    if (mt < mtMax) {
                        int ab = (s16 + mt * 64 + r4) * 40 + ks * 16 + 2 * c4;
                        u32 a0 = pack2h(*(const float2*)&Af[ab]);
                        u32 a1 = pack2h(*(const float2*)&Af[ab + 320]);
                        u32 a2 = pack2h(*(const float2*)&Af[ab + 8]);
                        u32 a3 = pack2h(*(const float2*)&Af[ab + 328]);
#pragma unroll
                        for (int nt = 0; nt < 8; nt++)
                            mma16(acc[mt][nt], a0, a1, a2, a3,
                                  b[nt][0], b[nt][1]);
                    }
                }
            }
        }
        CP_WAIT(0);

        if (MODE == 0) {
            // ---- fused SwiGLU epilogue: exchange up accs via smem ----
            float* xs = (float*)smem;
            __syncthreads();                    // pipeline smem now dead
            if (group == 1) {
#pragma unroll
                for (int mt = 0; mt < 4; mt++) {
                    int r = s16 + mt * 64 + r4;
#pragma unroll
                    for (int nt = 0; nt < 8; nt++) {
                        int col = nt * 8 + c4 * 2;
                        *(float2*)&xs[r * XSTR + col] =
                            make_float2(acc[mt][nt][0], acc[mt][nt][1]);
                        *(float2*)&xs[(r + 8) * XSTR + col] =
                            make_float2(acc[mt][nt][2], acc[mt][nt][3]);
                    }
                }
            }
            __syncthreads();
            if (group == 0) {
#pragma unroll
                for (int mt = 0; mt < 4; mt++) {
                    int r = s16 + mt * 64 + r4;
                    int rloc = m0 + r;
#pragma unroll
                    for (int nt = 0; nt < 8; nt++) {
                        int col = nt * 8 + c4 * 2;
                        if (rloc < cnt) {
                            float2 u = *(const float2*)&xs[r * XSTR + col];
                            float g0 = acc[mt][nt][0], g1 = acc[mt][nt][1];
                            float h0 = g0 / (1.f + __expf(-g0)) * u.x;
                            float h1 = g1 / (1.f + __expf(-g1)) * u.y;
                            *(float2*)&d_Hb[(long long)(row0e + rloc) * FF
                                            + n0 + col] = make_float2(h0, h1);
                        }
                        if (rloc + 8 < cnt) {
                            float2 u = *(const float2*)&xs[(r + 8) * XSTR + col];
                            float g0 = acc[mt][nt][2], g1 = acc[mt][nt][3];
                            float h0 = g0 / (1.f + __expf(-g0)) * u.x;
                            float h1 = g1 / (1.f + __expf(-g1)) * u.y;
                            *(float2*)&d_Hb[(long long)(row0e + rloc + 8) * FF
                                            + n0 + col] = make_float2(h0, h1);
                        }
                    }
                }
            }
        } else {
            // ---- weighted atomic scatter into Out ----
#pragma unroll
            for (int mt = 0; mt < 4; mt++) {
                int rloc = m0 + s16 + mt * 64 + r4;
                int v0 = rloc < cnt, v1 = (rloc + 8) < cnt;
                int t0 = 0, t1 = 0; float w0 = 0.f, w1 = 0.f;
                if (v0) { t0 = d_tok[row0e + rloc];     w0 = d_wts[row0e + rloc]; }
                if (v1) { t1 = d_tok[row0e + rloc + 8]; w1 = d_wts[row0e + rloc + 8]; }
#pragma unroll
                for (int nt = 0; nt < 8; nt++) {
                    int col = n0 + warpN + nt * 8 + c4 * 2;
                    if (v0) {
                        float* o = Out + (long long)t0 * HID + col;
                        atomicAdd(o,     w0 * acc[mt][nt][0]);
                        atomicAdd(o + 1, w0 * acc[mt][nt][1]);
                    }
                    if (v1) {
                        float* o = Out + (long long)t1 * HID + col;
                        atomicAdd(o,     w1 * acc[mt][nt][2]);
                        atomicAdd(o + 1, w1 * acc[mt][nt][3]);
                    }
                }
            }
        }
        __syncthreads();
#undef ISSUE
    }
}

// ---------------- launch ----------------------------------------------------
extern "C" void kernel_launch(void* const* d_in, const int* in_sizes, int n_in,
                              void* d_out, int out_size) {
    const float* x   = (const float*)d_in[0];
    const float* w1  = (const float*)d_in[1];
    const float* w2  = (const float*)d_in[2];
    const float* tw  = (const float*)d_in[3];
    const int*   ids = (const int*)d_in[4];
    float* out = (float*)d_out;

    cudaFuncSetAttribute(k_gemm<HID, 0>,
                         cudaFuncAttributeMaxDynamicSharedMemorySize, SMB);
    cudaFuncSetAttribute(k_gemm<FF, 1>,
                         cudaFuncAttributeMaxDynamicSharedMemorySize, SMB);

    k_zero_out<<<1024, 512>>>((float4*)out);
    k_prep<<<1, 256>>>(ids, tw);
    k_gemm<HID, 0><<<dim3(FF / 64, NEXP), 256, SMB>>>(x, w1, nullptr);
    k_gemm<FF, 1><<<dim3(HID / 128, NEXP), 256, SMB>>>(nullptr, w2, out);
}

// round 9
// speedup vs baseline: 1.0271x; 1.0271x over previous
#include <cuda_runtime.h>

// ---------------------------------------------------------------------------
// Fused MoE via grouped fp16 mma.sync (m16n8k16) GEMMs, fp32 accumulate.
//   T=1024, H=2048, F=1408, E=32, K=6.
// zero_out -> prep(one CTA) -> GEMM1 (gate+up, fused SwiGLU -> d_Hb)
//          -> GEMM2 (fused weighted atomic scatter -> out)
// 512 threads / 16 warps per CTA (4 per SMSP) for latency hiding; warp tile
// 64x32; M-stripes interleaved across SMSPs at 16-row grain.
// ---------------------------------------------------------------------------

#define T_TOK 1024
#define HID   2048
#define FF    1408
#define NEXP  32
#define TOPK  6
#define NA    (T_TOK * TOPK)    // 6144
#define GUN   (2 * FF)          // 2816

typedef unsigned int u32;

// smem: A 3 stages x 256 rows x 40 floats; B 3 stages x 128 rows x 40 floats
#define AST   40960u
#define BBASE 122880u
#define BST   20480u
#define SMB   184320
#define XSTR  68                // exchange stride (floats)

// ---------------- device scratch -------------------------------------------
__device__ int   d_count[NEXP];
__device__ int   d_off[NEXP];
__device__ int   d_tok[NA];
__device__ float d_wts[NA];
__device__ float d_Hb[(size_t)NA * FF];

// ---------------- PTX helpers ----------------------------------------------
__device__ __forceinline__ u32 smem_u32(const void* p) {
    u32 a;
    asm("{ .reg .u64 t; cvta.to.shared.u64 t, %1; cvt.u32.u64 %0, t; }"
        : "=r"(a) : "l"(p));
    return a;
}
__device__ __forceinline__ u32 pack2h(float2 v) {   // {lo=v.x, hi=v.y} fp16x2
    u32 r;
    asm("cvt.rn.f16x2.f32 %0, %1, %2;" : "=r"(r) : "f"(v.y), "f"(v.x));
    return r;
}
#define CP16(dst, src, sz) \
    asm volatile("cp.async.cg.shared.global [%0], [%1], 16, %2;" \
                 :: "r"(dst), "l"(src), "r"(sz))
#define CP_COMMIT() asm volatile("cp.async.commit_group;" ::: "memory")
#define CP_WAIT(n)  asm volatile("cp.async.wait_group %0;" :: "n"(n) : "memory")

__device__ __forceinline__ void mma16(float* d, u32 a0, u32 a1, u32 a2, u32 a3,
                                      u32 b0, u32 b1) {
    asm volatile(
        "mma.sync.aligned.m16n8k16.row.col.f32.f16.f16.f32 "
        "{%0,%1,%2,%3}, {%4,%5,%6,%7}, {%8,%9}, {%0,%1,%2,%3};"
        : "+f"(d[0]), "+f"(d[1]), "+f"(d[2]), "+f"(d[3])
        : "r"(a0), "r"(a1), "r"(a2), "r"(a3), "r"(b0), "r"(b1));
}

// ---------------- prep: detect + hist + scan + fill, one CTA ----------------
__global__ void k_zero_out(float4* out) {
    out[blockIdx.x * blockDim.x + threadIdx.x] = make_float4(0.f, 0.f, 0.f, 0.f);
}
__global__ __launch_bounds__(256) void k_prep(const int* __restrict__ ids32,
                                              const float* __restrict__ tw) {
    __shared__ int f;
    __shared__ int scnt[NEXP];
    __shared__ int sfill[NEXP];
    const int tid = threadIdx.x;
    if (tid < NEXP) scnt[tid] = 0;
    if (tid == 0) f = 0;
    __syncthreads();
    int local = 0;
    for (int i = tid; i < NA / 2; i += 256)
        if (ids32[2 * i + 1] != 0) local = 1;
    if (local) f = 1;
    __syncthreads();
    const int flag = f;   // 1 => int32 ids
    for (int i = tid; i < NA; i += 256) {
        int e = flag ? ids32[i] : ids32[2 * i];
        atomicAdd(&scnt[e], 1);
    }
    __syncthreads();
    if (tid == 0) {
        int off = 0;
        for (int e = 0; e < NEXP; e++) {
            d_off[e] = off; sfill[e] = off;
            d_count[e] = scnt[e];
            off += scnt[e];
        }
    }
    __syncthreads();
    for (int i = tid; i < NA; i += 256) {
        int e = flag ? ids32[i] : ids32[2 * i];
        int pos = atomicAdd(&sfill[e], 1);
        d_tok[pos] = i / TOPK;
        d_wts[pos] = tw[i];
    }
}

// ---------------- grouped fp16 GEMM ----------------------------------------
// BM=256, BK=32, 512 threads (16 warps). Warp tile 64x32: four 16-row stripes
// at rows (wid&3)*16 + mt*64, 32 cols at warpN=(wid>>2)*32.
// MODE 0: B tile = 64 gate rows + 64 up rows of same h-cols (n0=bx*64).
//   Groups 0,1 (warpN 0,32) = gate; groups 2,3 (warpN 64,96) = up.
//   Up groups park accs in smem; gate groups apply silu(g)*u -> d_Hb.
// MODE 1: BN=128 (n0=bx*128), weighted atomic scatter into Out.
template<int KDIM, int MODE>
__global__ __launch_bounds__(512, 1) void k_gemm(const float* __restrict__ Ain,
                                                 const float* __restrict__ Bw,
                                                 float* __restrict__ Out) {
    constexpr int NIT = KDIM / 32;
    extern __shared__ char smem[];
    const int e = blockIdx.y;
    const int cnt = d_count[e];
    if (cnt == 0) return;
    const int row0e = d_off[e];
    const int n0 = blockIdx.x * (MODE == 0 ? 64 : 128);
    const long long bStride = (MODE == 0) ? (long long)GUN * HID
                                          : (long long)HID * FF;
    const float* A = (MODE == 0) ? Ain : d_Hb;

    const int tid = threadIdx.x;
    const int wid = tid >> 5, lane = tid & 31;
    const int r4 = lane >> 2, c4 = lane & 3;
    const int s16   = (wid & 3) * 16;       // SMSP-interleaved M base
    const int group = wid >> 2;             // 0..3 N-group
    const int warpN = group * 32;
    const u32 sb = smem_u32(smem);

    // loader: 512 threads, chunk = 16B slot (8 per 128B row), rb = 0..63
    const int chunk = tid & 7, rb = tid >> 3;
    const float* bS[2];
    u32 bD[2];
#pragma unroll
    for (int p = 0; p < 2; p++) {
        int row = rb + 64 * p;
        long long gr = (MODE == 0)
            ? ((row < 64) ? (long long)(n0 + row) : (long long)(FF + n0 + row - 64))
            : (long long)(n0 + row);
        bS[p] = Bw + (long long)e * bStride + gr * KDIM + chunk * 4;
        bD[p] = sb + BBASE + (u32)row * 160u + (u32)chunk * 16u;
    }

    for (int m0 = 0; m0 < cnt; m0 += 256) {
        const float* aS[4];
        u32 aV[4], aD[4];
#pragma unroll
        for (int j = 0; j < 4; j++) {
            int r = rb + 64 * j;
            int valid = (m0 + r) < cnt;
            long long src = 0;
            if (valid)
                src = (MODE == 0) ? (long long)d_tok[row0e + m0 + r]
                                  : (long long)(row0e + m0 + r);
            aS[j] = A + src * KDIM + chunk * 4;
            aV[j] = valid ? 16u : 0u;
            aD[j] = sb + (u32)r * 160u + (u32)chunk * 16u;
        }
        const int rem = cnt - m0;
        const int tv = rem - s16;
        const int mtMax = (tv <= 0) ? 0 : ((tv + 63) >> 6 > 4 ? 4 : (tv + 63) >> 6);

        float acc[4][4][4];
#pragma unroll
        for (int mt = 0; mt < 4; mt++)
#pragma unroll
            for (int nt = 0; nt < 4; nt++)
#pragma unroll
                for (int q = 0; q < 4; q++) acc[mt][nt][q] = 0.f;

#define ISSUE(s, k0) do {                                                  \
        u32 _ao = (u32)(s) * AST;                                          \
        u32 _bo = (u32)(s) * BST;                                          \
        _Pragma("unroll")                                                  \
        for (int _j = 0; _j < 4; _j++)                                     \
            CP16(aD[_j] + _ao, aS[_j] + (k0), aV[_j]);                     \
        _Pragma("unroll")                                                  \
        for (int _p = 0; _p < 2; _p++)                                     \
            CP16(bD[_p] + _bo, bS[_p] + (k0), 16u);                        \
    } while (0)

        ISSUE(0, 0);  CP_COMMIT();
        ISSUE(1, 32); CP_COMMIT();

        for (int it = 0; it < NIT; it++) {
            const int buf = it % 3;
            CP_WAIT(1);
            __syncthreads();
            const int ns = it + 2;
            if (ns < NIT) ISSUE(ns % 3, ns * 32);
            CP_COMMIT();

            const float* Af = (const float*)(smem + buf * AST);
            const float* Bf = (const float*)(smem + BBASE + buf * BST);
#pragma unroll
            for (int ks = 0; ks < 2; ks++) {
                u32 b[4][2];
#pragma unroll
                for (int nt = 0; nt < 4; nt++) {
                    int cb = (warpN + nt * 8 + r4) * 40 + ks * 16 + 2 * c4;
                    b[nt][0] = pack2h(*(const float2*)&Bf[cb]);
                    b[nt][1] = pack2h(*(const float2*)&Bf[cb + 8]);
                }
#pragma unroll
                for (int mt = 0; mt < 4; mt++) {
                    if (mt < mtMax) {
                        int ab = (s16 + mt * 64 + r4) * 40 + ks * 16 + 2 * c4;
                        u32 a0 = pack2h(*(const float2*)&Af[ab]);
                        u32 a1 = pack2h(*(const float2*)&Af[ab + 320]);
                        u32 a2 = pack2h(*(const float2*)&Af[ab + 8]);
                        u32 a3 = pack2h(*(const float2*)&Af[ab + 328]);
#pragma unroll
                        for (int nt = 0; nt < 4; nt++)
                            mma16(acc[mt][nt], a0, a1, a2, a3,
                                  b[nt][0], b[nt][1]);
                    }
                }
            }
        }
        CP_WAIT(0);

        if (MODE == 0) {
            // ---- fused SwiGLU epilogue: up groups -> smem, gate groups read
            float* xs = (float*)smem;
            __syncthreads();                    // pipeline smem now dead
            if (group >= 2) {
                const int xc = (group - 2) * 32;
#pragma unroll
                for (int mt = 0; mt < 4; mt++) {
                    int r = s16 + mt * 64 + r4;
#pragma unroll
                    for (int nt = 0; nt < 4; nt++) {
                        int col = xc + nt * 8 + c4 * 2;
                        *(float2*)&xs[r * XSTR + col] =
                            make_float2(acc[mt][nt][0], acc[mt][nt][1]);
                        *(float2*)&xs[(r + 8) * XSTR + col] =
                            make_float2(acc[mt][nt][2], acc[mt][nt][3]);
                    }
                }
            }
            __syncthreads();
            if (group < 2) {
                const int xc = group * 32;
#pragma unroll
                for (int mt = 0; mt < 4; mt++) {
                    int r = s16 + mt * 64 + r4;
                    int rloc = m0 + r;
#pragma unroll
                    for (int nt = 0; nt < 4; nt++) {
                        int col = xc + nt * 8 + c4 * 2;
                        if (rloc < cnt) {
                            float2 u = *(const float2*)&xs[r * XSTR + col];
                            float g0 = acc[mt][nt][0], g1 = acc[mt][nt][1];
                            float h0 = g0 / (1.f + __expf(-g0)) * u.x;
                            float h1 = g1 / (1.f + __expf(-g1)) * u.y;
                            *(float2*)&d_Hb[(long long)(row0e + rloc) * FF
                                            + n0 + col] = make_float2(h0, h1);
                        }
                        if (rloc + 8 < cnt) {
                            float2 u = *(const float2*)&xs[(r + 8) * XSTR + col];
                            float g0 = acc[mt][nt][2], g1 = acc[mt][nt][3];
                            float h0 = g0 / (1.f + __expf(-g0)) * u.x;
                            float h1 = g1 / (1.f + __expf(-g1)) * u.y;
                            *(float2*)&d_Hb[(long long)(row0e + rloc + 8) * FF
                                            + n0 + col] = make_float2(h0, h1);
                        }
                    }
                }
            }
        } else {
            // ---- weighted atomic scatter into Out ----
#pragma unroll
            for (int mt = 0; mt < 4; mt++) {
                int rloc = m0 + s16 + mt * 64 + r4;
                int v0 = rloc < cnt, v1 = (rloc + 8) < cnt;
                int t0 = 0, t1 = 0; float w0 = 0.f, w1 = 0.f;
                if (v0) { t0 = d_tok[row0e + rloc];     w0 = d_wts[row0e + rloc]; }
                if (v1) { t1 = d_tok[row0e + rloc + 8]; w1 = d_wts[row0e + rloc + 8]; }
#pragma unroll
                for (int nt = 0; nt < 4; nt++) {
                    int col = n0 + warpN + nt * 8 + c4 * 2;
                    if (v0) {
                        float* o = Out + (long long)t0 * HID + col;
                        atomicAdd(o,     w0 * acc[mt][nt][0]);
                        atomicAdd(o + 1, w0 * acc[mt][nt][1]);
                    }
                    if (v1) {
                        float* o = Out + (long long)t1 * HID + col;
                        atomicAdd(o,     w1 * acc[mt][nt][2]);
                        atomicAdd(o + 1, w1 * acc[mt][nt][3]);
                    }
                }
            }
        }
        __syncthreads();
#undef ISSUE
    }
}

// ---------------- launch ----------------------------------------------------
extern "C" void kernel_launch(void* const* d_in, const int* in_sizes, int n_in,
                              void* d_out, int out_size) {
    const float* x   = (const float*)d_in[0];
    const float* w1  = (const float*)d_in[1];
    const float* w2  = (const float*)d_in[2];
    const float* tw  = (const float*)d_in[3];
    const int*   ids = (const int*)d_in[4];
    float* out = (float*)d_out;

    cudaFuncSetAttribute(k_gemm<HID, 0>,
                         cudaFuncAttributeMaxDynamicSharedMemorySize, SMB);
    cudaFuncSetAttribute(k_gemm<FF, 1>,
                         cudaFuncAttributeMaxDynamicSharedMemorySize, SMB);

    k_zero_out<<<1024, 512>>>((float4*)out);
    k_prep<<<1, 256>>>(ids, tw);
    k_gemm<HID, 0><<<dim3(FF / 64, NEXP), 512, SMB>>>(x, w1, nullptr);
    k_gemm<FF, 1><<<dim3(HID / 128, NEXP), 512, SMB>>>(nullptr, w2, out);
}

// round 10
// speedup vs baseline: 1.1832x; 1.1519x over previous
#include <cuda_runtime.h>
#include <cuda_fp16.h>

// ---------------------------------------------------------------------------
// Fused MoE via grouped fp16 mma.sync (m16n8k16) GEMMs, fp32 accumulate.
//   T=1024, H=2048, F=1408, E=32, K=6.
// zero_out -> prep -> x->fp16 -> GEMM1 (gate+up, fused SwiGLU -> Hb fp16)
//          -> GEMM2 (fused weighted atomic scatter -> out)
// A-side staged as fp16 (halves cp.async count - the measured bottleneck);
// B weights staged fp32 and converted at fragment load.
// ---------------------------------------------------------------------------

#define T_TOK 1024
#define HID   2048
#define FF    1408
#define NEXP  32
#define TOPK  6
#define NA    (T_TOK * TOPK)    // 6144
#define GUN   (2 * FF)          // 2816

typedef unsigned int u32;

// smem: 4 stages: A 256 rows x 40 halfs (80B) = 20KB; B 128 rows x 40 floats
// (160B) = 20KB.  A at [0,81920), B at [81920,163840).
#define AST   20480u
#define BBASE 81920u
#define BST   20480u
#define SMB   163840
#define XSTR  68                // swiglu exchange stride (floats)

// ---------------- device scratch -------------------------------------------
__device__ int    d_count[NEXP];
__device__ int    d_off[NEXP];
__device__ int    d_tok[NA];
__device__ float  d_wts[NA];
__device__ __half d_xh[(size_t)T_TOK * HID];   // x in fp16
__device__ __half d_Hh[(size_t)NA * FF];       // swiglu output in fp16

// ---------------- PTX helpers ----------------------------------------------
__device__ __forceinline__ u32 smem_u32(const void* p) {
    u32 a;
    asm("{ .reg .u64 t; cvta.to.shared.u64 t, %1; cvt.u32.u64 %0, t; }"
        : "=r"(a) : "l"(p));
    return a;
}
__device__ __forceinline__ u32 pack2h(float2 v) {   // {lo=v.x, hi=v.y} fp16x2
    u32 r;
    asm("cvt.rn.f16x2.f32 %0, %1, %2;" : "=r"(r) : "f"(v.y), "f"(v.x));
    return r;
}
#define CP16(dst, src, sz) \
    asm volatile("cp.async.cg.shared.global [%0], [%1], 16, %2;" \
                 :: "r"(dst), "l"(src), "r"(sz))
#define CP_COMMIT() asm volatile("cp.async.commit_group;" ::: "memory")
#define CP_WAIT(n)  asm volatile("cp.async.wait_group %0;" :: "n"(n) : "memory")

__device__ __forceinline__ void mma16(float* d, u32 a0, u32 a1, u32 a2, u32 a3,
                                      u32 b0, u32 b1) {
    asm volatile(
        "mma.sync.aligned.m16n8k16.row.col.f32.f16.f16.f32 "
        "{%0,%1,%2,%3}, {%4,%5,%6,%7}, {%8,%9}, {%0,%1,%2,%3};"
        : "+f"(d[0]), "+f"(d[1]), "+f"(d[2]), "+f"(d[3])
        : "r"(a0), "r"(a1), "r"(a2), "r"(a3), "r"(b0), "r"(b1));
}

// ---------------- prep / convert -------------------------------------------
__global__ void k_zero_out(float4* out) {
    out[blockIdx.x * blockDim.x + threadIdx.x] = make_float4(0.f, 0.f, 0.f, 0.f);
}
__global__ void k_x2h(const float2* __restrict__ x) {
    int i = blockIdx.x * blockDim.x + threadIdx.x;   // 1M threads, 2 el each
    float2 v = x[i];
    ((__half2*)d_xh)[i] = __floats2half2_rn(v.x, v.y);
}
__global__ __launch_bounds__(256) void k_prep(const int* __restrict__ ids32,
                                              const float* __restrict__ tw) {
    __shared__ int f;
    __shared__ int scnt[NEXP];
    __shared__ int sfill[NEXP];
    const int tid = threadIdx.x;
    if (tid < NEXP) scnt[tid] = 0;
    if (tid == 0) f = 0;
    __syncthreads();
    int local = 0;
    for (int i = tid; i < NA / 2; i += 256)
        if (ids32[2 * i + 1] != 0) local = 1;
    if (local) f = 1;
    __syncthreads();
    const int flag = f;   // 1 => int32 ids
    for (int i = tid; i < NA; i += 256) {
        int e = flag ? ids32[i] : ids32[2 * i];
        atomicAdd(&scnt[e], 1);
    }
    __syncthreads();
    if (tid == 0) {
        int off = 0;
        for (int e = 0; e < NEXP; e++) {
            d_off[e] = off; sfill[e] = off;
            d_count[e] = scnt[e];
            off += scnt[e];
        }
    }
    __syncthreads();
    for (int i = tid; i < NA; i += 256) {
        int e = flag ? ids32[i] : ids32[2 * i];
        int pos = atomicAdd(&sfill[e], 1);
        d_tok[pos] = i / TOPK;
        d_wts[pos] = tw[i];
    }
}

// ---------------- grouped fp16 GEMM ----------------------------------------
// BM=256, BK=32, 512 threads (16 warps). Warp tile 64x32: four 16-row stripes
// at rows (wid&3)*16 + mt*64 (SMSP-interleaved), 32 cols at warpN=(wid>>2)*32.
// A staged fp16 (gmem fp16), B staged fp32 + cvt at fragment load.
// MODE 0: B tile = 64 gate rows + 64 up rows of same h-cols (n0=bx*64);
//   groups 0,1 gate / 2,3 up; up accs -> smem; gate applies silu*u -> d_Hh.
// MODE 1: BN=128 (n0=bx*128), weighted atomic scatter into Out.
template<int KDIM, int MODE>
__global__ __launch_bounds__(512, 1) void k_gemm(const float* __restrict__ Bw,
                                                 float* __restrict__ Out) {
    constexpr int NIT = KDIM / 32;
    extern __shared__ char smem[];
    const int e = blockIdx.y;
    const int cnt = d_count[e];
    if (cnt == 0) return;
    const int row0e = d_off[e];
    const int n0 = blockIdx.x * (MODE == 0 ? 64 : 128);
    const long long bStride = (MODE == 0) ? (long long)GUN * HID
                                          : (long long)HID * FF;
    const __half* A = (MODE == 0) ? d_xh : d_Hh;

    const int tid = threadIdx.x;
    const int wid = tid >> 5, lane = tid & 31;
    const int r4 = lane >> 2, c4 = lane & 3;
    const int s16   = (wid & 3) * 16;       // SMSP-interleaved M base
    const int group = wid >> 2;             // 0..3 N-group
    const int warpN = group * 32;
    const u32 sb = smem_u32(smem);

    // B loader: chunk = 16B slot (8 per 128B row), rb = 0..63, 2 rows/thread
    const int chunk = tid & 7, rb = tid >> 3;
    const float* bS[2];
    u32 bD[2];
#pragma unroll
    for (int p = 0; p < 2; p++) {
        int row = rb + 64 * p;
        long long gr = (MODE == 0)
            ? ((row < 64) ? (long long)(n0 + row) : (long long)(FF + n0 + row - 64))
            : (long long)(n0 + row);
        bS[p] = Bw + (long long)e * bStride + gr * KDIM + chunk * 4;
        bD[p] = sb + BBASE + (u32)row * 160u + (u32)chunk * 16u;
    }

    for (int m0 = 0; m0 < cnt; m0 += 256) {
        // A loader: 1024 16B-slots (4 per 64B fp16 row), 2 slots/thread
        const __half* aS[2];
        u32 aV[2], aD[2];
#pragma unroll
        for (int j = 0; j < 2; j++) {
            int slot = tid + 512 * j;
            int r = slot >> 2, ch = slot & 3;
            int valid = (m0 + r) < cnt;
            long long src = 0;
            if (valid)
                src = (MODE == 0) ? (long long)d_tok[row0e + m0 + r]
                                  : (long long)(row0e + m0 + r);
            aS[j] = A + src * KDIM + ch * 8;
            aV[j] = valid ? 16u : 0u;
            aD[j] = sb + (u32)r * 80u + (u32)ch * 16u;
        }
        const int rem = cnt - m0;
        const int tv = rem - s16;
        const int mtMax = (tv <= 0) ? 0 : ((tv + 63) >> 6 > 4 ? 4 : (tv + 63) >> 6);

        float acc[4][4][4];
#pragma unroll
        for (int mt = 0; mt < 4; mt++)
#pragma unroll
            for (int nt = 0; nt < 4; nt++)
#pragma unroll
                for (int q = 0; q < 4; q++) acc[mt][nt][q] = 0.f;

#define ISSUE(s, k0) do {                                                  \
        u32 _ao = (u32)(s) * AST;                                          \
        u32 _bo = (u32)(s) * BST;                                          \
        _Pragma("unroll")                                                  \
        for (int _j = 0; _j < 2; _j++)                                     \
            CP16(aD[_j] + _ao, aS[_j] + (k0), aV[_j]);                     \
        _Pragma("unroll")                                                  \
        for (int _p = 0; _p < 2; _p++)                                     \
            CP16(bD[_p] + _bo, bS[_p] + (k0), 16u);                        \
    } while (0)

        ISSUE(0, 0);  CP_COMMIT();
        ISSUE(1, 32); CP_COMMIT();
        ISSUE(2, 64); CP_COMMIT();

        for (int it = 0; it < NIT; it++) {
            const int buf = it & 3;
            CP_WAIT(2);
            __syncthreads();
            const int ns = it + 3;
            if (ns < NIT) ISSUE(ns & 3, ns * 32);
            CP_COMMIT();

            const __half* Ah = (const __half*)(smem + buf * AST);
            const float*  Bf = (const float*)(smem + BBASE + buf * BST);
#pragma unroll
            for (int ks = 0; ks < 2; ks++) {
                u32 b[4][2];
#pragma unroll
                for (int nt = 0; nt < 4; nt++) {
                    int cb = (warpN + nt * 8 + r4) * 40 + ks * 16 + 2 * c4;
                    b[nt][0] = pack2h(*(const float2*)&Bf[cb]);
                    b[nt][1] = pack2h(*(const float2*)&Bf[cb + 8]);
                }
#pragma unroll
                for (int mt = 0; mt < 4; mt++) {
                    if (mt < mtMax) {
                        int ab = (s16 + mt * 64 + r4) * 40 + ks * 16 + 2 * c4;
                        u32 a0 = *(const u32*)&Ah[ab];          // fp16x2 direct
                        u32 a1 = *(const u32*)&Ah[ab + 320];    // +8 rows
                        u32 a2 = *(const u32*)&Ah[ab + 8];      // +8 k
                        u32 a3 = *(const u32*)&Ah[ab + 328];
#pragma unroll
                        for (int nt = 0; nt < 4; nt++)
                            mma16(acc[mt][nt], a0, a1, a2, a3,
                                  b[nt][0], b[nt][1]);
                    }
                }
            }
        }
        CP_WAIT(0);

        if (MODE == 0) {
            // ---- fused SwiGLU epilogue: up groups -> smem, gate groups read
            float* xs = (float*)smem;
            __syncthreads();                    // pipeline smem now dead
            if (group >= 2) {
                const int xc = (group - 2) * 32;
#pragma unroll
                for (int mt = 0; mt < 4; mt++) {
                    int r = s16 + mt * 64 + r4;
#pragma unroll
                    for (int nt = 0; nt < 4; nt++) {
                        int col = xc + nt * 8 + c4 * 2;
                        *(float2*)&xs[r * XSTR + col] =
                            make_float2(acc[mt][nt][0], acc[mt][nt][1]);
                        *(float2*)&xs[(r + 8) * XSTR + col] =
                            make_float2(acc[mt][nt][2], acc[mt][nt][3]);
                    }
                }
            }
            __syncthreads();
            if (group < 2) {
                const int xc = group * 32;
#pragma unroll
                for (int mt = 0; mt < 4; mt++) {
                    int r = s16 + mt * 64 + r4;
                    int rloc = m0 + r;
#pragma unroll
                    for (int nt = 0; nt < 4; nt++) {
                        int col = xc + nt * 8 + c4 * 2;
                        if (rloc < cnt) {
                            float2 u = *(const float2*)&xs[r * XSTR + col];
                            float g0 = acc[mt][nt][0], g1 = acc[mt][nt][1];
                            float h0 = g0 / (1.f + __expf(-g0)) * u.x;
                            float h1 = g1 / (1.f + __expf(-g1)) * u.y;
                            *(__half2*)&d_Hh[(long long)(row0e + rloc) * FF
                                + n0 + col] = __floats2half2_rn(h0, h1);
                        }
                        if (rloc + 8 < cnt) {
                            float2 u = *(const float2*)&xs[(r + 8) * XSTR + col];
                            float g0 = acc[mt][nt][2], g1 = acc[mt][nt][3];
                            float h0 = g0 / (1.f + __expf(-g0)) * u.x;
                            float h1 = g1 / (1.f + __expf(-g1)) * u.y;
                            *(__half2*)&d_Hh[(long long)(row0e + rloc + 8) * FF
                                + n0 + col] = __floats2half2_rn(h0, h1);
                        }
                    }
                }
            }
        } else {
            // ---- weighted atomic scatter into Out ----
#pragma unroll
            for (int mt = 0; mt < 4; mt++) {
                int rloc = m0 + s16 + mt * 64 + r4;
                int v0 = rloc < cnt, v1 = (rloc + 8) < cnt;
                int t0 = 0, t1 = 0; float w0 = 0.f, w1 = 0.f;
                if (v0) { t0 = d_tok[row0e + rloc];     w0 = d_wts[row0e + rloc]; }
                if (v1) { t1 = d_tok[row0e + rloc + 8]; w1 = d_wts[row0e + rloc + 8]; }
#pragma unroll
                for (int nt = 0; nt < 4; nt++) {
                    int col = n0 + warpN + nt * 8 + c4 * 2;
                    if (v0) {
                        float* o = Out + (long long)t0 * HID + col;
                        atomicAdd(o,     w0 * acc[mt][nt][0]);
                        atomicAdd(o + 1, w0 * acc[mt][nt][1]);
                    }
                    if (v1) {
                        float* o = Out + (long long)t1 * HID + col;
                        atomicAdd(o,     w1 * acc[mt][nt][2]);
                        atomicAdd(o + 1, w1 * acc[mt][nt][3]);
                    }
                }
            }
        }
        __syncthreads();
#undef ISSUE
    }
}

// ---------------- launch ----------------------------------------------------
extern "C" void kernel_launch(void* const* d_in, const int* in_sizes, int n_in,
                              void* d_out, int out_size) {
    const float* x   = (const float*)d_in[0];
    const float* w1  = (const float*)d_in[1];
    const float* w2  = (const float*)d_in[2];
    const float* tw  = (const float*)d_in[3];
    const int*   ids = (const int*)d_in[4];
    float* out = (float*)d_out;

    cudaFuncSetAttribute(k_gemm<HID, 0>,
                         cudaFuncAttributeMaxDynamicSharedMemorySize, SMB);
    cudaFuncSetAttribute(k_gemm<FF, 1>,
                         cudaFuncAttributeMaxDynamicSharedMemorySize, SMB);

    k_zero_out<<<1024, 512>>>((float4*)out);
    k_x2h<<<2048, 512>>>((const float2*)x);
    k_prep<<<1, 256>>>(ids, tw);
    k_gemm<HID, 0><<<dim3(FF / 64, NEXP), 512, SMB>>>(w1, nullptr);
    k_gemm<FF, 1><<<dim3(HID / 128, NEXP), 512, SMB>>>(w2, out);
}